// round 1
// baseline (speedup 1.0000x reference)
#include <cuda_runtime.h>
#include <cuda_bf16.h>

// STSEarlyFusionConcat: out (1, 2C, D, H, W) fp32
//   out[c,d,h,w]    = (w>=d) ? x[c,h,w]   : 0    for c in [0,C)
//   out[C+c,d,h,w]  = (w>=d) ? y[c,h,w-d] : 0    for c in [0,C)
// B=1, C=32, H=96, W=192, max_disp=192 -> D=64
// Pure HBM-write-bound: 302 MB out, ~4.5 MB in (L2 resident, 64x reuse).

namespace {
constexpr int C  = 32;
constexpr int H  = 96;
constexpr int W  = 192;
constexpr int D  = 64;
constexpr int W4 = W / 4;                          // 48 float4 per row
constexpr long long TOTAL4 = (long long)(2 * C) * D * H * W4;  // 18,874,368
}

__global__ __launch_bounds__(256)
void stsef_kernel(const float* __restrict__ x,
                  const float* __restrict__ y,
                  float4* __restrict__ out)
{
    unsigned idx = blockIdx.x * blockDim.x + threadIdx.x;
    // grid sized exactly; TOTAL4 divisible by 256, no tail check needed
    // decode: idx = ((c2*D + d)*H + h)*W4 + w4
    unsigned w4 = idx % W4;
    unsigned t  = idx / W4;
    unsigned h  = t % H;  t /= H;
    unsigned d  = t % D;  t /= D;
    unsigned c2 = t;                 // 0..63

    int w0 = (int)(w4 * 4);
    int dd = (int)d;
    float4 v;

    if (c2 < C) {
        // cost_x: aligned float4 load, predicated zero for w < d
        const float4* xr = reinterpret_cast<const float4*>(x + ((c2 * H) + h) * W);
        float4 xv = __ldg(&xr[w4]);
        v.x = (w0 + 0 >= dd) ? xv.x : 0.0f;
        v.y = (w0 + 1 >= dd) ? xv.y : 0.0f;
        v.z = (w0 + 2 >= dd) ? xv.z : 0.0f;
        v.w = (w0 + 3 >= dd) ? xv.w : 0.0f;
    } else {
        // cost_y: shifted read y[c,h,w-d]; scalar L2-hit loads (misaligned by d%4)
        unsigned c = c2 - C;
        const float* yr = y + ((c * H) + h) * W;
        v.x = (w0 + 0 >= dd) ? __ldg(yr + (w0 + 0 - dd)) : 0.0f;
        v.y = (w0 + 1 >= dd) ? __ldg(yr + (w0 + 1 - dd)) : 0.0f;
        v.z = (w0 + 2 >= dd) ? __ldg(yr + (w0 + 2 - dd)) : 0.0f;
        v.w = (w0 + 3 >= dd) ? __ldg(yr + (w0 + 3 - dd)) : 0.0f;
    }

    out[idx] = v;
}

extern "C" void kernel_launch(void* const* d_in, const int* in_sizes, int n_in,
                              void* d_out, int out_size)
{
    const float* x = (const float*)d_in[0];
    const float* y = (const float*)d_in[1];
    // d_in[2] is max_disp (scalar) — compile-time constant here
    float4* out = (float4*)d_out;

    const int threads = 256;
    const long long blocks = TOTAL4 / threads;     // 73,728
    stsef_kernel<<<(unsigned)blocks, threads>>>(x, y, out);
}

// round 2
// speedup vs baseline: 1.3719x; 1.3719x over previous
#include <cuda_runtime.h>
#include <cuda_bf16.h>

// STSEarlyFusionConcat: out (1, 2C, D, H, W) fp32
//   out[c,d,h,w]    = (w>=d) ? x[c,h,w]   : 0    for c in [0,C)
//   out[C+c,d,h,w]  = (w>=d) ? y[c,h,w-d] : 0    for c in [0,C)
// B=1, C=32, H=96, W=192, D=64.  HBM-write-bound: 302 MB out.
// R2: each thread produces 4 consecutive d-values for one (c2,h,w4):
//   x: 1 LDG.128 -> 4 masked STG.128
//   y: 7 predicated scalar loads cover all 4 shifted windows (mask == load predicate)

namespace {
constexpr int C   = 32;
constexpr int H   = 96;
constexpr int W   = 192;
constexpr int D   = 64;
constexpr int W4  = W / 4;                 // 48
constexpr int DQ  = D / 4;                 // 16
constexpr long long NTHREADS = (long long)(2 * C) * DQ * H * W4;  // 4,718,592
}

__global__ __launch_bounds__(256)
void stsef_kernel(const float* __restrict__ x,
                  const float* __restrict__ y,
                  float4* __restrict__ out)
{
    unsigned idx = blockIdx.x * blockDim.x + threadIdx.x;
    // idx = ((c2*DQ + dq)*H + h)*W4 + w4
    unsigned w4 = idx % W4;
    unsigned t  = idx / W4;
    unsigned h  = t % H;   t /= H;
    unsigned dq = t % DQ;  t /= DQ;
    unsigned c2 = t;                        // 0..63

    int w0 = (int)(w4 * 4);
    int d0 = (int)(dq * 4);

    size_t obase = (((size_t)(c2 * D + d0) * H) + h) * W4 + w4;  // float4 index
    const size_t dstr = (size_t)H * W4;                          // stride per d

    if (c2 < C) {
        // cost_x: one aligned vector load, 4 masked streaming stores
        const float4* xr = reinterpret_cast<const float4*>(x + ((c2 * H) + h) * W);
        float4 xv = __ldg(xr + w4);
#pragma unroll
        for (int k = 0; k < 4; k++) {
            int dd = d0 + k;
            float4 v;
            v.x = (w0 + 0 >= dd) ? xv.x : 0.0f;
            v.y = (w0 + 1 >= dd) ? xv.y : 0.0f;
            v.z = (w0 + 2 >= dd) ? xv.z : 0.0f;
            v.w = (w0 + 3 >= dd) ? xv.w : 0.0f;
            __stcs(out + obase + (size_t)k * dstr, v);
        }
    } else {
        // cost_y: 7 scalars y[b-3 .. b+3] (b = w0-d0) cover the 4 shifted windows.
        // Load predicate (e >= 0) doubles as the validity mask.
        const float* yr = y + (((c2 - C) * H) + h) * W;
        int b = w0 - d0;
        float tv[7];
#pragma unroll
        for (int i = 0; i < 7; i++) {
            int e = b - 3 + i;
            tv[i] = (e >= 0) ? __ldg(yr + e) : 0.0f;
        }
#pragma unroll
        for (int k = 0; k < 4; k++) {
            // component j of store k = y[b + j - k] = tv[3 + j - k]
            float4 v;
            v.x = tv[3 - k];
            v.y = tv[4 - k];
            v.z = tv[5 - k];
            v.w = tv[6 - k];
            __stcs(out + obase + (size_t)k * dstr, v);
        }
    }
}

extern "C" void kernel_launch(void* const* d_in, const int* in_sizes, int n_in,
                              void* d_out, int out_size)
{
    const float* x = (const float*)d_in[0];
    const float* y = (const float*)d_in[1];
    float4* out = (float4*)d_out;

    const int threads = 256;
    const unsigned blocks = (unsigned)(NTHREADS / threads);  // 18,432
    stsef_kernel<<<blocks, threads>>>(x, y, out);
}